// round 2
// baseline (speedup 1.0000x reference)
#include <cuda_runtime.h>

// Problem constants (fixed by dataset)
#define DD    128        // feature dim
#define KK2   256        // concat K = 2*D
#define NMAX  50000

// Scratch (device globals: allocations are forbidden)
__device__ float g_h0[NMAX * DD];      // layer-0 features (gathered emb)
__device__ float g_h1[NMAX * DD];      // layer-1 output (post relu)
__device__ float g_neigh[NMAX * DD];   // scatter accumulator
__device__ float g_nb[NMAX * DD];      // neigh / max(deg,1)
__device__ float g_deg[NMAX];
__device__ float g_B1[KK2 * DD];       // [Ws1ᵀ ; Wn1ᵀ] concat, row-major [256][128]
__device__ float g_B2[KK2 * DD];

// ---------------------------------------------------------------------------
// h0 = emb[node_ids]; zero neigh accumulator and degree
// ---------------------------------------------------------------------------
__global__ void k_init(const int* __restrict__ node_ids,
                       const float* __restrict__ emb, int N)
{
    int total = N * DD;
    for (int i = blockIdx.x * blockDim.x + threadIdx.x; i < total;
         i += gridDim.x * blockDim.x) {
        int n = i >> 7;
        int k = i & 127;
        g_h0[i]    = emb[(size_t)node_ids[n] * DD + k];
        g_neigh[i] = 0.0f;
        if (i < N) g_deg[i] = 0.0f;
    }
}

// ---------------------------------------------------------------------------
// Build Bcat[k][j] = k<128 ? W_self[j][k] : W_neigh[j][k-128]  (both layers)
// ---------------------------------------------------------------------------
__global__ void k_transB(const float* __restrict__ Ws1, const float* __restrict__ Wn1,
                         const float* __restrict__ Ws2, const float* __restrict__ Wn2)
{
    int i = blockIdx.x * blockDim.x + threadIdx.x;   // 2 * 256 * 128 = 65536
    if (i >= 2 * KK2 * DD) return;
    int l = i >> 15;
    int r = i & 32767;
    int k = r >> 7;
    int j = r & 127;
    const float* Ws = l ? Ws2 : Ws1;
    const float* Wn = l ? Wn2 : Wn1;
    float v = (k < DD) ? Ws[j * DD + k] : Wn[j * DD + (k - DD)];
    (l ? g_B2 : g_B1)[r] = v;
}

// ---------------------------------------------------------------------------
// Scatter: one warp per edge. neigh[dst] += w * h[src] via RED.128.
// ---------------------------------------------------------------------------
__global__ void k_scatter(const float* __restrict__ h,
                          const int* __restrict__ src,
                          const int* __restrict__ dst,
                          const float* __restrict__ w,
                          int E, int count_deg)
{
    int gw   = (blockIdx.x * blockDim.x + threadIdx.x) >> 5;
    int lane = threadIdx.x & 31;
    if (gw >= E) return;

    int   s  = src[gw];
    int   t  = dst[gw];
    float we = w[gw];

    if (count_deg && lane == 0) atomicAdd(&g_deg[t], 1.0f);

    float4 v = *reinterpret_cast<const float4*>(h + (size_t)s * DD + lane * 4);
    v.x *= we; v.y *= we; v.z *= we; v.w *= we;
    float* p = g_neigh + (size_t)t * DD + lane * 4;
#if defined(__CUDA_ARCH__) && __CUDA_ARCH__ >= 900
    atomicAdd(reinterpret_cast<float4*>(p), v);      // single RED.E.ADD.128
#else
    atomicAdd(p + 0, v.x); atomicAdd(p + 1, v.y);
    atomicAdd(p + 2, v.z); atomicAdd(p + 3, v.w);
#endif
}

// ---------------------------------------------------------------------------
// nb = neigh / max(deg,1);  re-zero neigh for the next layer
// ---------------------------------------------------------------------------
__global__ void k_prep(int N)
{
    int total = N * DD;
    for (int i = blockIdx.x * blockDim.x + threadIdx.x; i < total;
         i += gridDim.x * blockDim.x) {
        int n = i >> 7;
        float inv = 1.0f / fmaxf(g_deg[n], 1.0f);
        g_nb[i]    = g_neigh[i] * inv;
        g_neigh[i] = 0.0f;
    }
}

// ---------------------------------------------------------------------------
// Fused GEMM: out[M x 128] = [h | nb][M x 256] @ Bcat[256 x 128] + bias
// 128x128 tile, BK=16, 8x8 register blocking, double-buffered static smem.
// Thread (tx=tid&15, ty=tid>>4) owns rows {ty+16r} x cols {tx+16j}.
// ---------------------------------------------------------------------------
#define APAD 129   // As row pitch (scalar stores, bank-spread)
#define BPAD 132   // Bs row pitch (keeps 16B alignment for float4 STS)

__global__ void __launch_bounds__(256, 2)
k_gemm(const float* __restrict__ hmat, const float* __restrict__ nbmat,
       const float* __restrict__ Bcat, const float* __restrict__ bias,
       float* __restrict__ out, int M, int do_relu)
{
    __shared__ float As[2][16 * APAD];
    __shared__ float Bs[2][16 * BPAD];

    int tid = threadIdx.x;
    int m0  = blockIdx.x * 128;
    int tx  = tid & 15;
    int ty  = tid >> 4;

    // A-loader mapping: fidx -> (row mA, 4 consecutive k)
    // B-loader mapping: fidx -> (k row, 4 consecutive j)
    auto ldA = [&](int c, int slot) -> float4 {
        int fidx = tid + slot * 256;
        int m    = fidx >> 2;
        int k4   = (fidx & 3) << 2;
        const float* src = (c < 8) ? hmat : nbmat;
        int row = m0 + m;
        if (row < M)
            return *reinterpret_cast<const float4*>(
                src + (size_t)row * DD + (c & 7) * 16 + k4);
        return make_float4(0.f, 0.f, 0.f, 0.f);
    };
    auto stA = [&](int buf, int slot, float4 v) {
        int fidx = tid + slot * 256;
        int m    = fidx >> 2;
        int k4   = (fidx & 3) << 2;
        float* p = &As[buf][0];
        p[(k4 + 0) * APAD + m] = v.x;
        p[(k4 + 1) * APAD + m] = v.y;
        p[(k4 + 2) * APAD + m] = v.z;
        p[(k4 + 3) * APAD + m] = v.w;
    };
    auto ldB = [&](int c, int slot) -> float4 {
        int fidx = tid + slot * 256;
        int k    = fidx >> 5;
        int j4   = (fidx & 31) << 2;
        return *reinterpret_cast<const float4*>(
            Bcat + (size_t)(c * 16 + k) * DD + j4);
    };
    auto stB = [&](int buf, int slot, float4 v) {
        int fidx = tid + slot * 256;
        int k    = fidx >> 5;
        int j4   = (fidx & 31) << 2;
        *reinterpret_cast<float4*>(&Bs[buf][k * BPAD + j4]) = v;
    };

    float acc[8][8];
#pragma unroll
    for (int r = 0; r < 8; ++r)
#pragma unroll
        for (int j = 0; j < 8; ++j) acc[r][j] = 0.0f;

    float4 a0 = ldA(0, 0), a1 = ldA(0, 1);
    float4 b0 = ldB(0, 0), b1 = ldB(0, 1);
    stA(0, 0, a0); stA(0, 1, a1);
    stB(0, 0, b0); stB(0, 1, b1);
    __syncthreads();

    for (int c = 0; c < 16; ++c) {
        int buf = c & 1;
        if (c < 15) {
            a0 = ldA(c + 1, 0); a1 = ldA(c + 1, 1);
            b0 = ldB(c + 1, 0); b1 = ldB(c + 1, 1);
        }
        const float* Ap = &As[buf][0];
        const float* Bp = &Bs[buf][0];
#pragma unroll
        for (int k = 0; k < 16; ++k) {
            float a[8], b[8];
#pragma unroll
            for (int r = 0; r < 8; ++r) a[r] = Ap[k * APAD + ty + 16 * r];
#pragma unroll
            for (int j = 0; j < 8; ++j) b[j] = Bp[k * BPAD + tx + 16 * j];
#pragma unroll
            for (int r = 0; r < 8; ++r)
#pragma unroll
                for (int j = 0; j < 8; ++j) acc[r][j] += a[r] * b[j];
        }
        if (c < 15) {
            int nb2 = buf ^ 1;
            stA(nb2, 0, a0); stA(nb2, 1, a1);
            stB(nb2, 0, b0); stB(nb2, 1, b1);
        }
        __syncthreads();
    }

    float bb[8];
#pragma unroll
    for (int j = 0; j < 8; ++j) bb[j] = bias[tx + 16 * j];

#pragma unroll
    for (int r = 0; r < 8; ++r) {
        int m = m0 + ty + 16 * r;
        if (m < M) {
#pragma unroll
            for (int j = 0; j < 8; ++j) {
                float v = acc[r][j] + bb[j];
                if (do_relu) v = fmaxf(v, 0.0f);
                out[(size_t)m * DD + tx + 16 * j] = v;
            }
        }
    }
}

// ---------------------------------------------------------------------------
// init -> transB -> [scatter -> prep -> gemm] x 2
// Inputs: node_ids, edge_src, edge_dst, edge_weight, emb,
//         W_self1, W_neigh1, b1, W_self2, W_neigh2, b2
// ---------------------------------------------------------------------------
extern "C" void kernel_launch(void* const* d_in, const int* in_sizes, int n_in,
                              void* d_out, int out_size)
{
    const int*   node_ids = (const int*)  d_in[0];
    const int*   esrc     = (const int*)  d_in[1];
    const int*   edst     = (const int*)  d_in[2];
    const float* ew       = (const float*)d_in[3];
    const float* emb      = (const float*)d_in[4];
    const float* Ws1      = (const float*)d_in[5];
    const float* Wn1      = (const float*)d_in[6];
    const float* b1       = (const float*)d_in[7];
    const float* Ws2      = (const float*)d_in[8];
    const float* Wn2      = (const float*)d_in[9];
    const float* b2       = (const float*)d_in[10];

    int N = in_sizes[0];
    int E = in_sizes[1];
    float* out = (float*)d_out;

    void *p_h0_v, *p_h1_v, *p_nb_v, *p_B1_v, *p_B2_v;
    cudaGetSymbolAddress(&p_h0_v, g_h0);
    cudaGetSymbolAddress(&p_h1_v, g_h1);
    cudaGetSymbolAddress(&p_nb_v, g_nb);
    cudaGetSymbolAddress(&p_B1_v, g_B1);
    cudaGetSymbolAddress(&p_B2_v, g_B2);
    const float* p_h0 = (const float*)p_h0_v;
    const float* p_h1 = (const float*)p_h1_v;
    const float* p_nb = (const float*)p_nb_v;
    const float* p_B1 = (const float*)p_B1_v;
    const float* p_B2 = (const float*)p_B2_v;

    const int TB = 256;
    int sblocks = (E + 7) / 8;                 // 8 warps (edges) per block
    int gblocks = (N + 127) / 128;

    k_init<<<2048, TB>>>(node_ids, emb, N);
    k_transB<<<(2 * KK2 * DD + TB - 1) / TB, TB>>>(Ws1, Wn1, Ws2, Wn2);

    // Layer 1
    k_scatter<<<sblocks, TB>>>(p_h0, esrc, edst, ew, E, 1);
    k_prep<<<2048, TB>>>(N);
    k_gemm<<<gblocks, TB>>>(p_h0, p_nb, p_B1, b1, (float*)p_h1_v, N, 1);

    // Layer 2
    k_scatter<<<sblocks, TB>>>(p_h1, esrc, edst, ew, E, 0);
    k_prep<<<2048, TB>>>(N);
    k_gemm<<<gblocks, TB>>>(p_h1, p_nb, p_B2, b2, out, N, 0);
}

// round 3
// speedup vs baseline: 1.1276x; 1.1276x over previous
#include <cuda_runtime.h>

// Problem constants (fixed by dataset)
#define DD    128        // feature dim
#define KK2   256        // concat K = 2*D
#define NMAX  50048      // padded

// Scratch (device globals: allocations are forbidden)
__device__ float g_h0[NMAX * DD];      // layer-0 features (gathered emb)
__device__ float g_h1[NMAX * DD];      // layer-1 output (post relu)
__device__ float g_neigh1[NMAX * DD];  // scatter accumulator, layer 1
__device__ float g_neigh2[NMAX * DD];  // scatter accumulator, layer 2
__device__ float g_deg[NMAX];
__device__ float g_B1[KK2 * DD];       // [Ws1ᵀ ; Wn1ᵀ] concat, row-major [256][128]
__device__ float g_B2[KK2 * DD];

// ---------------------------------------------------------------------------
// h0 = emb[node_ids]; zero both neigh accumulators and degree
// ---------------------------------------------------------------------------
__global__ void k_init(const int* __restrict__ node_ids,
                       const float* __restrict__ emb, int N)
{
    int total = N * DD;
    for (int i = blockIdx.x * blockDim.x + threadIdx.x; i < total;
         i += gridDim.x * blockDim.x) {
        int n = i >> 7;
        int k = i & 127;
        g_h0[i]     = emb[(size_t)node_ids[n] * DD + k];
        g_neigh1[i] = 0.0f;
        g_neigh2[i] = 0.0f;
        if (i < N) g_deg[i] = 0.0f;
    }
}

// ---------------------------------------------------------------------------
// Bcat[k][j] = k<128 ? W_self[j][k] : W_neigh[j][k-128]   (both layers)
// ---------------------------------------------------------------------------
__global__ void k_transB(const float* __restrict__ Ws1, const float* __restrict__ Wn1,
                         const float* __restrict__ Ws2, const float* __restrict__ Wn2)
{
    int i = blockIdx.x * blockDim.x + threadIdx.x;   // 2 * 256 * 128
    if (i >= 2 * KK2 * DD) return;
    int l = i >> 15;
    int r = i & 32767;
    int k = r >> 7;
    int j = r & 127;
    const float* Ws = l ? Ws2 : Ws1;
    const float* Wn = l ? Wn2 : Wn1;
    float v = (k < DD) ? Ws[j * DD + k] : Wn[j * DD + (k - DD)];
    (l ? g_B2 : g_B1)[r] = v;
}

// ---------------------------------------------------------------------------
// Scatter: one warp per edge. neigh[dst] += w * h[src] via RED.128
// ---------------------------------------------------------------------------
__global__ void k_scatter(const float* __restrict__ h,
                          const int* __restrict__ src,
                          const int* __restrict__ dst,
                          const float* __restrict__ w,
                          float* __restrict__ neigh,
                          int E, int count_deg)
{
    int gw   = (blockIdx.x * blockDim.x + threadIdx.x) >> 5;
    int lane = threadIdx.x & 31;
    if (gw >= E) return;

    int   s  = src[gw];
    int   t  = dst[gw];
    float we = w[gw];

    if (count_deg && lane == 0) atomicAdd(&g_deg[t], 1.0f);

    float4 v = *reinterpret_cast<const float4*>(h + (size_t)s * DD + lane * 4);
    v.x *= we; v.y *= we; v.z *= we; v.w *= we;
    float* p = neigh + (size_t)t * DD + lane * 4;
#if defined(__CUDA_ARCH__) && __CUDA_ARCH__ >= 900
    atomicAdd(reinterpret_cast<float4*>(p), v);
#else
    atomicAdd(p + 0, v.x); atomicAdd(p + 1, v.y);
    atomicAdd(p + 2, v.z); atomicAdd(p + 3, v.w);
#endif
}

// ---------------------------------------------------------------------------
// Tensor-core GEMM (3xTF32): out[M x 128] = [h | neigh/deg][M x 256] @ Bcat + bias
// 128x128 tile, TK=32, 8 warps (4 m x 2 n), warp tile 32m x 64n.
// mma.sync.m16n8k8.tf32; D = Ahi*Bhi + Ahi*Blo + Alo*Bhi  (fp32-accurate).
// Smem pitches: As 36 (bank=4g+t), Bs 136 (bank=8t+g) -> conflict-free frags.
// ---------------------------------------------------------------------------
#define AP 36
#define BP 136

__device__ __forceinline__ unsigned f2tf(float x)
{
    unsigned r;
    asm("cvt.rna.tf32.f32 %0, %1;" : "=r"(r) : "f"(x));
    return r;
}

__device__ __forceinline__ void mma8(float* d, const unsigned* a, const unsigned* b)
{
    asm volatile(
        "mma.sync.aligned.m16n8k8.row.col.f32.tf32.tf32.f32 "
        "{%0,%1,%2,%3}, {%4,%5,%6,%7}, {%8,%9}, {%0,%1,%2,%3};"
        : "+f"(d[0]), "+f"(d[1]), "+f"(d[2]), "+f"(d[3])
        : "r"(a[0]), "r"(a[1]), "r"(a[2]), "r"(a[3]), "r"(b[0]), "r"(b[1]));
}

__global__ void __launch_bounds__(256)
k_gemm(const float* __restrict__ hmat, const float* __restrict__ nmat,
       const float* __restrict__ Bcat, const float* __restrict__ bias,
       float* __restrict__ out, int M, int do_relu)
{
    __shared__ float As[128 * AP];   // [m][k] pitch 36
    __shared__ float Bs[32 * BP];    // [k][n] pitch 136

    int tid  = threadIdx.x;
    int m0   = blockIdx.x * 128;
    int wid  = tid >> 5;
    int lane = tid & 31;
    int wm   = wid & 3;              // 0..3 : rows wm*32..+31
    int wn   = wid >> 2;             // 0..1 : cols wn*64..+63
    int g    = lane >> 2;            // groupID
    int t    = lane & 3;             // threadID_in_group

    // per-thread A-loader rows (4 slots) and their 1/max(deg,1)
    float invd[4];
#pragma unroll
    for (int s = 0; s < 4; ++s) {
        int row = m0 + (tid >> 3) + 32 * s;
        float d = (row < M) ? g_deg[row] : 1.0f;
        invd[s] = 1.0f / fmaxf(d, 1.0f);
    }

    float acc[2][8][4];
#pragma unroll
    for (int mt = 0; mt < 2; ++mt)
#pragma unroll
        for (int nt = 0; nt < 8; ++nt)
#pragma unroll
            for (int v = 0; v < 4; ++v) acc[mt][nt][v] = 0.0f;

    auto ldgA = [&](int c, int s) -> float4 {
        int fidx = tid + s * 256;
        int m    = fidx >> 3;
        int kq   = fidx & 7;
        int gk   = c * 32 + 4 * kq;
        int row  = m0 + m;
        if (row >= M) return make_float4(0.f, 0.f, 0.f, 0.f);
        if (gk < DD)
            return *reinterpret_cast<const float4*>(hmat + (size_t)row * DD + gk);
        float4 v = *reinterpret_cast<const float4*>(nmat + (size_t)row * DD + gk - DD);
        float iv = invd[s];
        v.x *= iv; v.y *= iv; v.z *= iv; v.w *= iv;
        return v;
    };
    auto ldgB = [&](int c, int s) -> float4 {
        int fidx = tid + s * 256;
        int k    = fidx >> 5;
        int nq   = fidx & 31;
        return *reinterpret_cast<const float4*>(
            Bcat + (size_t)(c * 32 + k) * DD + 4 * nq);
    };

    float4 ra[4], rb[4];
#pragma unroll
    for (int s = 0; s < 4; ++s) { ra[s] = ldgA(0, s); rb[s] = ldgB(0, s); }

    for (int c = 0; c < 8; ++c) {
        __syncthreads();   // previous compute done, smem reusable
#pragma unroll
        for (int s = 0; s < 4; ++s) {
            int fa = tid + s * 256;
            *reinterpret_cast<float4*>(&As[(fa >> 3) * AP + 4 * (fa & 7)]) = ra[s];
            int fb = tid + s * 256;
            *reinterpret_cast<float4*>(&Bs[(fb >> 5) * BP + 4 * (fb & 31)]) = rb[s];
        }
        __syncthreads();
        if (c < 7) {
#pragma unroll
            for (int s = 0; s < 4; ++s) { ra[s] = ldgA(c + 1, s); rb[s] = ldgB(c + 1, s); }
        }

#pragma unroll
        for (int kk = 0; kk < 4; ++kk) {
            int kc = kk * 8;
            unsigned ahi[2][4], alo[2][4];
#pragma unroll
            for (int mt = 0; mt < 2; ++mt) {
                int rm = wm * 32 + mt * 16;
                float a0 = As[(rm + g) * AP + kc + t];
                float a1 = As[(rm + g + 8) * AP + kc + t];
                float a2 = As[(rm + g) * AP + kc + t + 4];
                float a3 = As[(rm + g + 8) * AP + kc + t + 4];
                ahi[mt][0] = f2tf(a0); alo[mt][0] = f2tf(a0 - __uint_as_float(ahi[mt][0]));
                ahi[mt][1] = f2tf(a1); alo[mt][1] = f2tf(a1 - __uint_as_float(ahi[mt][1]));
                ahi[mt][2] = f2tf(a2); alo[mt][2] = f2tf(a2 - __uint_as_float(ahi[mt][2]));
                ahi[mt][3] = f2tf(a3); alo[mt][3] = f2tf(a3 - __uint_as_float(ahi[mt][3]));
            }
#pragma unroll
            for (int nt = 0; nt < 8; ++nt) {
                int cn = wn * 64 + nt * 8 + g;
                float b0f = Bs[(kc + t) * BP + cn];
                float b1f = Bs[(kc + t + 4) * BP + cn];
                unsigned bhi[2], blo[2];
                bhi[0] = f2tf(b0f); blo[0] = f2tf(b0f - __uint_as_float(bhi[0]));
                bhi[1] = f2tf(b1f); blo[1] = f2tf(b1f - __uint_as_float(bhi[1]));
#pragma unroll
                for (int mt = 0; mt < 2; ++mt) {
                    mma8(acc[mt][nt], ahi[mt], bhi);
                    mma8(acc[mt][nt], ahi[mt], blo);
                    mma8(acc[mt][nt], alo[mt], bhi);
                }
            }
        }
    }

    // Epilogue: bias (+relu), float2 stores
#pragma unroll
    for (int nt = 0; nt < 8; ++nt) {
        int col = wn * 64 + nt * 8 + 2 * t;
        float bx = bias[col], by = bias[col + 1];
#pragma unroll
        for (int mt = 0; mt < 2; ++mt) {
#pragma unroll
            for (int half = 0; half < 2; ++half) {
                int row = m0 + wm * 32 + mt * 16 + g + 8 * half;
                if (row < M) {
                    float vx = acc[mt][nt][2 * half + 0] + bx;
                    float vy = acc[mt][nt][2 * half + 1] + by;
                    if (do_relu) { vx = fmaxf(vx, 0.f); vy = fmaxf(vy, 0.f); }
                    *reinterpret_cast<float2*>(out + (size_t)row * DD + col)
                        = make_float2(vx, vy);
                }
            }
        }
    }
}

// ---------------------------------------------------------------------------
// init -> transB -> scatter1 -> gemm1 -> scatter2 -> gemm2
// Inputs: node_ids, edge_src, edge_dst, edge_weight, emb,
//         W_self1, W_neigh1, b1, W_self2, W_neigh2, b2
// ---------------------------------------------------------------------------
extern "C" void kernel_launch(void* const* d_in, const int* in_sizes, int n_in,
                              void* d_out, int out_size)
{
    const int*   node_ids = (const int*)  d_in[0];
    const int*   esrc     = (const int*)  d_in[1];
    const int*   edst     = (const int*)  d_in[2];
    const float* ew       = (const float*)d_in[3];
    const float* emb      = (const float*)d_in[4];
    const float* Ws1      = (const float*)d_in[5];
    const float* Wn1      = (const float*)d_in[6];
    const float* b1       = (const float*)d_in[7];
    const float* Ws2      = (const float*)d_in[8];
    const float* Wn2      = (const float*)d_in[9];
    const float* b2       = (const float*)d_in[10];

    int N = in_sizes[0];
    int E = in_sizes[1];
    float* out = (float*)d_out;

    void *p_h0_v, *p_h1_v, *p_n1_v, *p_n2_v, *p_B1_v, *p_B2_v;
    cudaGetSymbolAddress(&p_h0_v, g_h0);
    cudaGetSymbolAddress(&p_h1_v, g_h1);
    cudaGetSymbolAddress(&p_n1_v, g_neigh1);
    cudaGetSymbolAddress(&p_n2_v, g_neigh2);
    cudaGetSymbolAddress(&p_B1_v, g_B1);
    cudaGetSymbolAddress(&p_B2_v, g_B2);
    const float* p_h0 = (const float*)p_h0_v;
    const float* p_h1 = (const float*)p_h1_v;
    const float* p_n1 = (const float*)p_n1_v;
    const float* p_n2 = (const float*)p_n2_v;

    const int TB = 256;
    int sblocks = (E + 7) / 8;
    int gblocks = (N + 127) / 128;

    k_init<<<2048, TB>>>(node_ids, emb, N);
    k_transB<<<(2 * KK2 * DD + TB - 1) / TB, TB>>>(Ws1, Wn1, Ws2, Wn2);

    // Layer 1
    k_scatter<<<sblocks, TB>>>(p_h0, esrc, edst, ew, (float*)p_n1_v, E, 1);
    k_gemm<<<gblocks, TB>>>(p_h0, p_n1, (const float*)p_B1_v, b1,
                            (float*)p_h1_v, N, 1);

    // Layer 2
    k_scatter<<<sblocks, TB>>>(p_h1, esrc, edst, ew, (float*)p_n2_v, E, 0);
    k_gemm<<<gblocks, TB>>>(p_h1, p_n2, (const float*)p_B2_v, b2,
                            out, N, 0);
}